// round 1
// baseline (speedup 1.0000x reference)
#include <cuda_runtime.h>

#define SEQ 2048
#define DIM 4096
#define NH 32
#define NKV 8
#define HD 128
#define KVD 1024   // NKV*HD

typedef unsigned long long u64;

// ---------------- scratch (device globals: allowed per skill rules) ----------------
__device__ float g_xq[SEQ * DIM];
__device__ float g_xk[SEQ * KVD];
__device__ float g_xv[SEQ * KVD];
__device__ float g_att[SEQ * DIM];

// ---------------- packed f32x2 helpers (B300: FFMA2 = 2x FFMA throughput) ----------
__device__ __forceinline__ u64 dup2(float x) {
    unsigned u = __float_as_uint(x);
    u64 d;
    asm("mov.b64 %0, {%1, %1};" : "=l"(d) : "r"(u));
    return d;
}
__device__ __forceinline__ u64 ffma2(u64 a, u64 b, u64 c) {
    u64 d;
    asm("fma.rn.f32x2 %0, %1, %2, %3;" : "=l"(d) : "l"(a), "l"(b), "l"(c));
    return d;
}
__device__ __forceinline__ u64 fmul2(u64 a, u64 b) {
    u64 d;
    asm("mul.rn.f32x2 %0, %1, %2;" : "=l"(d) : "l"(a), "l"(b));
    return d;
}
__device__ __forceinline__ void unpk2(u64 a, float& x, float& y) {
    unsigned lo, hi;
    asm("mov.b64 {%0, %1}, %2;" : "=r"(lo), "=r"(hi) : "l"(a));
    x = __uint_as_float(lo);
    y = __uint_as_float(hi);
}

// ---------------- f32x2 SGEMM: C[M,N] = A[M,K] @ B[K,N], all row-major --------------
// BM=BN=128, BK=16, 256 threads, 8x8 microtile, accumulators paired along N.
#define GBM 128
#define GBN 128
#define GBK 16
#define APAD 132

__global__ __launch_bounds__(256, 2)
void sgemm_f32x2(const float* __restrict__ A, const float* __restrict__ B,
                 float* __restrict__ C, int M, int N, int K) {
    __shared__ float As[GBK][APAD];   // As[k][m], padded -> ~2-way store conflicts
    __shared__ float Bs[GBK][GBN];    // Bs[k][n], natural

    const int tid = threadIdx.x;
    const int tx = tid & 15;
    const int ty = tid >> 4;
    const int m0 = blockIdx.y * GBM;
    const int n0 = blockIdx.x * GBN;

    // A load mapping: row = tid>>2 (0..63) (+64 for second fetch), kq = (tid&3)*4
    const int arow = tid >> 2;
    const int akq = (tid & 3) * 4;
    // B load mapping: krow = tid>>5 (0..7) (+8), n = (tid&31)*4
    const int bk = tid >> 5;
    const int bn = (tid & 31) * 4;

    const float* Ag0 = A + (size_t)(m0 + arow) * K + akq;
    const float* Ag1 = A + (size_t)(m0 + arow + 64) * K + akq;
    const float* Bg0 = B + (size_t)bk * N + n0 + bn;
    const float* Bg1 = B + (size_t)(bk + 8) * N + n0 + bn;

    u64 acc[8][4];
#pragma unroll
    for (int i = 0; i < 8; i++)
#pragma unroll
        for (int j = 0; j < 4; j++) acc[i][j] = 0ull;

    float4 a0 = *(const float4*)(Ag0);
    float4 a1 = *(const float4*)(Ag1);
    float4 b0 = *(const float4*)(Bg0);
    float4 b1 = *(const float4*)(Bg1);

    const int nkt = K / GBK;
    for (int kt = 0; kt < nkt; kt++) {
        // stage -> smem
        As[akq + 0][arow] = a0.x;
        As[akq + 1][arow] = a0.y;
        As[akq + 2][arow] = a0.z;
        As[akq + 3][arow] = a0.w;
        As[akq + 0][arow + 64] = a1.x;
        As[akq + 1][arow + 64] = a1.y;
        As[akq + 2][arow + 64] = a1.z;
        As[akq + 3][arow + 64] = a1.w;
        *(float4*)&Bs[bk][bn] = b0;
        *(float4*)&Bs[bk + 8][bn] = b1;
        __syncthreads();

        if (kt + 1 < nkt) {  // prefetch next tile (global latency hidden by compute)
            a0 = *(const float4*)(Ag0 + (kt + 1) * GBK);
            a1 = *(const float4*)(Ag1 + (kt + 1) * GBK);
            b0 = *(const float4*)(Bg0 + (size_t)(kt + 1) * GBK * N);
            b1 = *(const float4*)(Bg1 + (size_t)(kt + 1) * GBK * N);
        }

#pragma unroll
        for (int k = 0; k < GBK; k++) {
            float a[8];
            *(float4*)&a[0] = *(const float4*)&As[k][ty * 8];
            *(float4*)&a[4] = *(const float4*)&As[k][ty * 8 + 4];
            const u64* brow = (const u64*)&Bs[k][0];
            u64 bp[4];
#pragma unroll
            for (int j = 0; j < 4; j++) bp[j] = brow[tx * 4 + j];
#pragma unroll
            for (int i = 0; i < 8; i++) {
                u64 ad = dup2(a[i]);
#pragma unroll
                for (int j = 0; j < 4; j++) acc[i][j] = ffma2(ad, bp[j], acc[i][j]);
            }
        }
        __syncthreads();
    }

#pragma unroll
    for (int i = 0; i < 8; i++) {
        float out[8];
#pragma unroll
        for (int j = 0; j < 4; j++) unpk2(acc[i][j], out[2 * j], out[2 * j + 1]);
        float* dst = C + (size_t)(m0 + ty * 8 + i) * N + n0 + tx * 8;
        *(float4*)dst = *(float4*)&out[0];
        *(float4*)(dst + 4) = *(float4*)&out[4];
    }
}

// ---------------- RoPE (interleaved pairs, cos/sin per (pos, i)) --------------------
__global__ void rope_kernel(float* __restrict__ x, const float* __restrict__ cs,
                            const float* __restrict__ sn, int nheads) {
    int idx = blockIdx.x * blockDim.x + threadIdx.x;
    int total = SEQ * nheads * (HD / 2);
    if (idx >= total) return;
    int i = idx & 63;
    int t = idx >> 6;
    int h = t % nheads;
    int pos = t / nheads;
    float c = cs[pos * 64 + i];
    float s = sn[pos * 64 + i];
    float2* p = (float2*)(x + (size_t)(pos * nheads + h) * HD) + i;
    float2 v = *p;
    float2 o;
    o.x = v.x * c - v.y * s;
    o.y = v.x * s + v.y * c;
    *p = o;
}

// ---------------- flash attention: 64q x 64k tiles, online softmax ------------------
#define BQ 64
#define BKV 64
#define SPAD 65

__global__ __launch_bounds__(256)
void attn_kernel(const float* __restrict__ XQ, const float* __restrict__ XK,
                 const float* __restrict__ XV, float* __restrict__ O) {
    extern __shared__ float sm[];
    float* Qs = sm;                 // [128][64]  (d-major)
    float* Ks = Qs + 128 * 64;      // [128][64]  (d-major)
    float* Vs = Ks + 128 * 64;      // [64][128]  (natural)
    float* Ss = Vs + 64 * 128;      // [64][SPAD]
    float* mrow = Ss + 64 * SPAD;   // [64]
    float* lrow = mrow + 64;        // [64]
    float* frow = lrow + 64;        // [64]

    const int tid = threadIdx.x;
    const int tx = tid & 15;
    const int ty = tid >> 4;
    const int lane = tid & 31;
    const int warp = tid >> 5;
    const int h = blockIdx.y;
    const int qt = (gridDim.x - 1) - blockIdx.x;   // long tiles launch first
    const int q0 = qt * BQ;
    const int kvh = h >> 2;                        // GQA: 4 query heads per kv head

    const float NEG_INF = __int_as_float(0xff800000);

    // Load Q tile: lanes along q (conflict-free transposed smem stores)
    {
        int qq = tid & 63;
        int dq0 = tid >> 6;  // 0..3
        const float* src = XQ + (size_t)(q0 + qq) * DIM + h * HD;
#pragma unroll
        for (int r = 0; r < 8; r++) {
            int dq = dq0 + r * 4;
            float4 v = *(const float4*)(src + dq * 4);
            Qs[(dq * 4 + 0) * 64 + qq] = v.x;
            Qs[(dq * 4 + 1) * 64 + qq] = v.y;
            Qs[(dq * 4 + 2) * 64 + qq] = v.z;
            Qs[(dq * 4 + 3) * 64 + qq] = v.w;
        }
    }
    if (tid < 64) {
        mrow[tid] = NEG_INF;
        lrow[tid] = 0.f;
    }

    u64 oacc[4][4];
#pragma unroll
    for (int i = 0; i < 4; i++)
#pragma unroll
        for (int j = 0; j < 4; j++) oacc[i][j] = 0ull;

    const int ntiles = qt + 1;
    for (int t = 0; t < ntiles; t++) {
        const int k0 = t * BKV;
        __syncthreads();  // previous PV done (and Q/m-l init visible after next sync)

        // Load K tile: lanes along k (conflict-free transposed stores, L2-served gathers)
        {
            int kk = tid & 63;
            int dq0 = tid >> 6;
            const float* src = XK + (size_t)(k0 + kk) * KVD + kvh * HD;
#pragma unroll
            for (int r = 0; r < 8; r++) {
                int dq = dq0 + r * 4;
                float4 v = *(const float4*)(src + dq * 4);
                Ks[(dq * 4 + 0) * 64 + kk] = v.x;
                Ks[(dq * 4 + 1) * 64 + kk] = v.y;
                Ks[(dq * 4 + 2) * 64 + kk] = v.z;
                Ks[(dq * 4 + 3) * 64 + kk] = v.w;
            }
        }
        // Load V tile: natural layout, coalesced
        {
            int kk0 = tid >> 5;   // 0..7
            int dq = tid & 31;
            const float* src = XV + (size_t)kvh * HD + dq * 4;
#pragma unroll
            for (int r = 0; r < 8; r++) {
                int kk = kk0 + r * 8;
                float4 v = *(const float4*)(src + (size_t)(k0 + kk) * KVD);
                *(float4*)&Vs[kk * 128 + dq * 4] = v;
            }
        }
        __syncthreads();

        // S = Q @ K^T (4x4 microtile, f32x2 paired along k-cols)
        u64 sa[4][2];
#pragma unroll
        for (int i = 0; i < 4; i++) { sa[i][0] = 0ull; sa[i][1] = 0ull; }
#pragma unroll 8
        for (int d = 0; d < 128; d++) {
            float qv[4];
            *(float4*)qv = *(const float4*)&Qs[d * 64 + ty * 4];
            const u64* krow = (const u64*)&Ks[d * 64];
            u64 kp0 = krow[tx * 2];
            u64 kp1 = krow[tx * 2 + 1];
#pragma unroll
            for (int i = 0; i < 4; i++) {
                u64 qd = dup2(qv[i]);
                sa[i][0] = ffma2(qd, kp0, sa[i][0]);
                sa[i][1] = ffma2(qd, kp1, sa[i][1]);
            }
        }
        const float scale = 0.08838834764831845f;  // 1/sqrt(128)
#pragma unroll
        for (int i = 0; i < 4; i++) {
            float s[4];
            unpk2(sa[i][0], s[0], s[1]);
            unpk2(sa[i][1], s[2], s[3]);
            int qg = q0 + ty * 4 + i;
#pragma unroll
            for (int j = 0; j < 4; j++) {
                int kg = k0 + tx * 4 + j;
                float v = s[j] * scale;
                if (kg > qg) v = NEG_INF;  // causal
                Ss[(ty * 4 + i) * SPAD + tx * 4 + j] = v;
            }
        }
        __syncthreads();

        // Online softmax: warp w owns rows w*8 .. w*8+7
#pragma unroll
        for (int rr = 0; rr < 8; rr++) {
            int r = warp * 8 + rr;
            float v1 = Ss[r * SPAD + lane];
            float v2 = Ss[r * SPAD + lane + 32];
            float mx = fmaxf(v1, v2);
#pragma unroll
            for (int off = 16; off; off >>= 1)
                mx = fmaxf(mx, __shfl_xor_sync(0xffffffffu, mx, off));
            float mold = mrow[r];
            float mnew = fmaxf(mold, mx);
            float p1 = __expf(v1 - mnew);
            float p2 = __expf(v2 - mnew);
            float s = p1 + p2;
#pragma unroll
            for (int off = 16; off; off >>= 1)
                s += __shfl_xor_sync(0xffffffffu, s, off);
            Ss[r * SPAD + lane] = p1;
            Ss[r * SPAD + lane + 32] = p2;
            if (lane == 0) {
                float f = __expf(mold - mnew);
                frow[r] = f;
                lrow[r] = lrow[r] * f + s;
                mrow[r] = mnew;
            }
        }
        __syncthreads();

        // O = O*f + P @ V (4x8 microtile as f32x2 pairs along d)
#pragma unroll
        for (int i = 0; i < 4; i++) {
            u64 fd = dup2(frow[ty * 4 + i]);
#pragma unroll
            for (int j = 0; j < 4; j++) oacc[i][j] = fmul2(oacc[i][j], fd);
        }
#pragma unroll 4
        for (int kk = 0; kk < BKV; kk++) {
            float p[4];
#pragma unroll
            for (int i = 0; i < 4; i++) p[i] = Ss[(ty * 4 + i) * SPAD + kk];
            const u64* vrow = (const u64*)&Vs[kk * 128];
            u64 vp[4];
#pragma unroll
            for (int j = 0; j < 4; j++) vp[j] = vrow[tx * 4 + j];
#pragma unroll
            for (int i = 0; i < 4; i++) {
                u64 pd = dup2(p[i]);
#pragma unroll
                for (int j = 0; j < 4; j++) oacc[i][j] = ffma2(pd, vp[j], oacc[i][j]);
            }
        }
    }

    // Epilogue: normalize by l and write attn_out[(q, h*128 + d)]
#pragma unroll
    for (int i = 0; i < 4; i++) {
        int qg = q0 + ty * 4 + i;
        float rl = 1.0f / lrow[ty * 4 + i];
        float out[8];
#pragma unroll
        for (int j = 0; j < 4; j++) {
            float x, y;
            unpk2(oacc[i][j], x, y);
            out[2 * j] = x * rl;
            out[2 * j + 1] = y * rl;
        }
        float* dst = O + (size_t)qg * DIM + h * HD + tx * 8;
        *(float4*)dst = *(float4*)&out[0];
        *(float4*)(dst + 4) = *(float4*)&out[4];
    }
}

// ---------------- launch --------------------------------------------------------
extern "C" void kernel_launch(void* const* d_in, const int* in_sizes, int n_in,
                              void* d_out, int out_size) {
    const float* x  = (const float*)d_in[0];
    const float* wq = (const float*)d_in[1];
    const float* wk = (const float*)d_in[2];
    const float* wv = (const float*)d_in[3];
    const float* wo = (const float*)d_in[4];
    const float* fc = (const float*)d_in[5];
    const float* fs = (const float*)d_in[6];
    // d_in[7] mask, d_in[8..9] caches, d_in[10] start_pos: causal + start_pos=0 handled analytically
    float* out = (float*)d_out;

    float *xq, *xk, *xv, *att;
    cudaGetSymbolAddress((void**)&xq, g_xq);
    cudaGetSymbolAddress((void**)&xk, g_xk);
    cudaGetSymbolAddress((void**)&xv, g_xv);
    cudaGetSymbolAddress((void**)&att, g_att);

    dim3 blk(256);
    sgemm_f32x2<<<dim3(DIM / GBN, SEQ / GBM), blk>>>(x, wq, xq, SEQ, DIM, DIM);
    sgemm_f32x2<<<dim3(KVD / GBN, SEQ / GBM), blk>>>(x, wk, xk, SEQ, KVD, DIM);
    sgemm_f32x2<<<dim3(KVD / GBN, SEQ / GBM), blk>>>(x, wv, xv, SEQ, KVD, DIM);

    rope_kernel<<<(SEQ * NH * 64 + 255) / 256, 256>>>(xq, fc, fs, NH);
    rope_kernel<<<(SEQ * NKV * 64 + 255) / 256, 256>>>(xk, fc, fs, NKV);

    int smem_bytes = (128 * 64 + 128 * 64 + 64 * 128 + 64 * SPAD + 3 * 64) * (int)sizeof(float);
    cudaFuncSetAttribute(attn_kernel, cudaFuncAttributeMaxDynamicSharedMemorySize, smem_bytes);
    attn_kernel<<<dim3(SEQ / BQ, NH), blk, smem_bytes>>>(xq, xk, xv, att);

    sgemm_f32x2<<<dim3(DIM / GBN, SEQ / GBM), blk>>>(att, wo, out, SEQ, DIM, DIM);
}

// round 3
// speedup vs baseline: 1.5794x; 1.5794x over previous
#include <cuda_runtime.h>
#include <cuda_bf16.h>
#include <cstdint>

#define SEQ 2048
#define DIM 4096
#define NH 32
#define NKV 8
#define HD 128
#define KVD 1024   // NKV*HD

typedef unsigned long long u64;

// ---------------- scratch (device globals) ----------------
__device__ float g_xq[SEQ * DIM];
__device__ float g_xk[SEQ * KVD];
__device__ float g_xv[SEQ * KVD];
__device__ float g_att[SEQ * DIM];

// bf16 hi/lo split scratch (activations, row-major [M,K])
__device__ __align__(128) __nv_bfloat16 g_xh[SEQ * DIM];
__device__ __align__(128) __nv_bfloat16 g_xl[SEQ * DIM];
__device__ __align__(128) __nv_bfloat16 g_ah[SEQ * DIM];
__device__ __align__(128) __nv_bfloat16 g_al[SEQ * DIM];
// transposed weights [N,K] bf16 hi/lo
__device__ __align__(128) __nv_bfloat16 g_wqh[DIM * DIM];
__device__ __align__(128) __nv_bfloat16 g_wql[DIM * DIM];
__device__ __align__(128) __nv_bfloat16 g_wkh[KVD * DIM];
__device__ __align__(128) __nv_bfloat16 g_wkl[KVD * DIM];
__device__ __align__(128) __nv_bfloat16 g_wvh[KVD * DIM];
__device__ __align__(128) __nv_bfloat16 g_wvl[KVD * DIM];
__device__ __align__(128) __nv_bfloat16 g_woh[DIM * DIM];
__device__ __align__(128) __nv_bfloat16 g_wol[DIM * DIM];

// ---------------- PTX helpers (baseline-PTX only: sm_80-class) ----------------
__device__ __forceinline__ uint32_t smem_u32(const void* p) {
    uint32_t a;
    asm("{ .reg .u64 t; cvta.to.shared.u64 t, %1; cvt.u32.u64 %0, t; }" : "=r"(a) : "l"(p));
    return a;
}
__device__ __forceinline__ void cpa16(uint32_t s, const void* g) {
    asm volatile("cp.async.cg.shared.global [%0], [%1], 16;" :: "r"(s), "l"(g));
}
__device__ __forceinline__ void ldsm4(unsigned* r, uint32_t addr) {
    asm volatile("ldmatrix.sync.aligned.m8n8.x4.shared.b16 {%0,%1,%2,%3}, [%4];"
                 : "=r"(r[0]), "=r"(r[1]), "=r"(r[2]), "=r"(r[3]) : "r"(addr));
}
__device__ __forceinline__ void ldsm2(unsigned* r, uint32_t addr) {
    asm volatile("ldmatrix.sync.aligned.m8n8.x2.shared.b16 {%0,%1}, [%2];"
                 : "=r"(r[0]), "=r"(r[1]) : "r"(addr));
}
__device__ __forceinline__ void mma16816(float* d, const unsigned* a, const unsigned* b) {
    asm volatile(
        "mma.sync.aligned.m16n8k16.row.col.f32.bf16.bf16.f32 "
        "{%0,%1,%2,%3}, {%4,%5,%6,%7}, {%8,%9}, {%0,%1,%2,%3};"
        : "+f"(d[0]), "+f"(d[1]), "+f"(d[2]), "+f"(d[3])
        : "r"(a[0]), "r"(a[1]), "r"(a[2]), "r"(a[3]), "r"(b[0]), "r"(b[1]));
}

// ---------------- packed f32x2 helpers (attention) ----------
__device__ __forceinline__ u64 dup2(float x) {
    unsigned u = __float_as_uint(x);
    u64 d;
    asm("mov.b64 %0, {%1, %1};" : "=l"(d) : "r"(u));
    return d;
}
__device__ __forceinline__ u64 ffma2(u64 a, u64 b, u64 c) {
    u64 d;
    asm("fma.rn.f32x2 %0, %1, %2, %3;" : "=l"(d) : "l"(a), "l"(b), "l"(c));
    return d;
}
__device__ __forceinline__ u64 fmul2(u64 a, u64 b) {
    u64 d;
    asm("mul.rn.f32x2 %0, %1, %2;" : "=l"(d) : "l"(a), "l"(b));
    return d;
}
__device__ __forceinline__ void unpk2(u64 a, float& x, float& y) {
    unsigned lo, hi;
    asm("mov.b64 {%0, %1}, %2;" : "=r"(lo), "=r"(hi) : "l"(a));
    x = __uint_as_float(lo);
    y = __uint_as_float(hi);
}

// ---------------- conversion kernels ----------------
__global__ void split_kernel(const float* __restrict__ x, __nv_bfloat16* __restrict__ h,
                             __nv_bfloat16* __restrict__ l, int n) {
    int i = blockIdx.x * blockDim.x + threadIdx.x;
    if (i >= n) return;
    float v = x[i];
    __nv_bfloat16 hi = __float2bfloat16(v);
    __nv_bfloat16 lo = __float2bfloat16(v - __bfloat162float(hi));
    h[i] = hi;
    l[i] = lo;
}

// w [K,N] f32 -> out [N,K] bf16 hi/lo
__global__ void transpose_split(const float* __restrict__ w, __nv_bfloat16* __restrict__ th,
                                __nv_bfloat16* __restrict__ tl, int K, int N) {
    __shared__ float tile[32][33];
    int k0 = blockIdx.y * 32, n0 = blockIdx.x * 32;
    int tx = threadIdx.x, ty = threadIdx.y;   // 32 x 8
#pragma unroll
    for (int r = 0; r < 4; r++)
        tile[ty + r * 8][tx] = w[(size_t)(k0 + ty + r * 8) * N + n0 + tx];
    __syncthreads();
#pragma unroll
    for (int r = 0; r < 4; r++) {
        float v = tile[tx][ty + r * 8];
        __nv_bfloat16 hi = __float2bfloat16(v);
        __nv_bfloat16 lo = __float2bfloat16(v - __bfloat162float(hi));
        size_t o = (size_t)(n0 + ty + r * 8) * K + k0 + tx;
        th[o] = hi;
        tl[o] = lo;
    }
}

// ---------------- HMMA bf16x3 GEMM: C[M,N] = A[M,K] @ B[N,K]^T ----------------
// CTA 128x128, BK=32, 8 warps (4m x 2n), warp tile 32x64, double-buffered cp.async.
#define BM 128
#define BN 128
#define BK 32
#define LDE 40                     // padded bf16 per smem row (80B stride: LDSM conflict-free)
#define ARR (128 * LDE * 2)        // 10240 B per array
#define STG (4 * ARR)              // 40960 B per stage (Ah,Al,Bh,Bl)
#define SMEM_GEMM (2 * STG)        // 81920 B

__global__ __launch_bounds__(256, 2)
void gemm_hmma(const __nv_bfloat16* __restrict__ Ah, const __nv_bfloat16* __restrict__ Al,
               const __nv_bfloat16* __restrict__ Bh, const __nv_bfloat16* __restrict__ Bl,
               float* __restrict__ C, int M, int N, int K) {
    extern __shared__ char smem[];
    const uint32_t sb = smem_u32(smem);
    const int tid = threadIdx.x;
    const int lane = tid & 31, warp = tid >> 5;
    const int m0 = blockIdx.y * BM, n0 = blockIdx.x * BN;
    const int wm = (warp & 3) * 32, wn = (warp >> 2) * 64;

    // load mapping: thread -> one 32B segment of one row per array
    const int lrow = tid >> 1;
    const int lc = (tid & 1) * 2;  // 16B-chunk index (0 or 2)
    const __nv_bfloat16* gah = Ah + (size_t)(m0 + lrow) * K + lc * 8;
    const __nv_bfloat16* gal = Al + (size_t)(m0 + lrow) * K + lc * 8;
    const __nv_bfloat16* gbh = Bh + (size_t)(n0 + lrow) * K + lc * 8;
    const __nv_bfloat16* gbl = Bl + (size_t)(n0 + lrow) * K + lc * 8;
    const uint32_t srow = (uint32_t)lrow * (LDE * 2) + lc * 16;

    float acc[2][8][4];
#pragma unroll
    for (int m = 0; m < 2; m++)
#pragma unroll
        for (int j = 0; j < 8; j++)
#pragma unroll
            for (int v = 0; v < 4; v++) acc[m][j][v] = 0.f;

    auto load_stage = [&](int buf, int ko) {
        uint32_t s0 = sb + buf * STG + srow;
        cpa16(s0, gah + ko);
        cpa16(s0 + 16, gah + ko + 8);
        cpa16(s0 + ARR, gal + ko);
        cpa16(s0 + ARR + 16, gal + ko + 8);
        cpa16(s0 + 2 * ARR, gbh + ko);
        cpa16(s0 + 2 * ARR + 16, gbh + ko + 8);
        cpa16(s0 + 3 * ARR, gbl + ko);
        cpa16(s0 + 3 * ARR + 16, gbl + ko + 8);
        asm volatile("cp.async.commit_group;");
    };

    load_stage(0, 0);
    const int NS = K / BK;
#pragma unroll 1
    for (int s = 0; s < NS; s++) {
        if (s + 1 < NS) {
            load_stage((s + 1) & 1, (s + 1) * BK);
            asm volatile("cp.async.wait_group 1;");
        } else {
            asm volatile("cp.async.wait_group 0;");
        }
        __syncthreads();

        const uint32_t base = sb + (s & 1) * STG;
#pragma unroll
        for (int ks = 0; ks < 2; ks++) {
            const int k0 = ks * 16;
            // A fragments (hi+lo) for both m sub-tiles, kept resident
            unsigned ah[2][4], al[2][4];
#pragma unroll
            for (int m = 0; m < 2; m++) {
                uint32_t aa = base +
                    (uint32_t)(wm + m * 16 + (lane & 15)) * (LDE * 2) +
                    (uint32_t)(k0 + (lane >> 4) * 8) * 2;
                ldsm4(ah[m], aa);
                ldsm4(al[m], aa + ARR);
            }
#pragma unroll
            for (int j = 0; j < 8; j++) {
                uint32_t ba = base + 2 * ARR +
                    (uint32_t)(wn + j * 8 + (lane & 7)) * (LDE * 2) +
                    (uint32_t)(k0 + ((lane >> 3) & 1) * 8) * 2;
                unsigned bh[2], bl[2];
                ldsm2(bh, ba);
                ldsm2(bl, ba + ARR);
#pragma unroll
                for (int m = 0; m < 2; m++) {
                    mma16816(acc[m][j], ah[m], bh);
                    mma16816(acc[m][j], ah[m], bl);
                    mma16816(acc[m][j], al[m], bh);
                }
            }
        }
        __syncthreads();
    }

    // epilogue: fragment layout -> C
#pragma unroll
    for (int m = 0; m < 2; m++) {
        int r0 = m0 + wm + m * 16 + (lane >> 2);
#pragma unroll
        for (int j = 0; j < 8; j++) {
            int c = n0 + wn + j * 8 + (lane & 3) * 2;
            float2 v0 = make_float2(acc[m][j][0], acc[m][j][1]);
            float2 v1 = make_float2(acc[m][j][2], acc[m][j][3]);
            *(float2*)(C + (size_t)r0 * N + c) = v0;
            *(float2*)(C + (size_t)(r0 + 8) * N + c) = v1;
        }
    }
}

// ---------------- RoPE ----------------
__global__ void rope_kernel(float* __restrict__ x, const float* __restrict__ cs,
                            const float* __restrict__ sn, int nheads) {
    int idx = blockIdx.x * blockDim.x + threadIdx.x;
    int total = SEQ * nheads * (HD / 2);
    if (idx >= total) return;
    int i = idx & 63;
    int t = idx >> 6;
    int h = t % nheads;
    int pos = t / nheads;
    float c = cs[pos * 64 + i];
    float s = sn[pos * 64 + i];
    float2* p = (float2*)(x + (size_t)(pos * nheads + h) * HD) + i;
    float2 v = *p;
    float2 o;
    o.x = v.x * c - v.y * s;
    o.y = v.x * s + v.y * c;
    *p = o;
}

// ---------------- flash attention (f32x2 SIMT, unchanged) ----------------
#define BQ 64
#define BKV 64
#define SPAD 65

__global__ __launch_bounds__(256)
void attn_kernel(const float* __restrict__ XQ, const float* __restrict__ XK,
                 const float* __restrict__ XV, float* __restrict__ O) {
    extern __shared__ float sm[];
    float* Qs = sm;
    float* Ks = Qs + 128 * 64;
    float* Vs = Ks + 128 * 64;
    float* Ss = Vs + 64 * 128;
    float* mrow = Ss + 64 * SPAD;
    float* lrow = mrow + 64;
    float* frow = lrow + 64;

    const int tid = threadIdx.x;
    const int tx = tid & 15;
    const int ty = tid >> 4;
    const int lane = tid & 31;
    const int warp = tid >> 5;
    const int h = blockIdx.y;
    const int qt = (gridDim.x - 1) - blockIdx.x;
    const int q0 = qt * BQ;
    const int kvh = h >> 2;

    const float NEG_INF = __int_as_float(0xff800000);

    {
        int qq = tid & 63;
        int dq0 = tid >> 6;
        const float* src = XQ + (size_t)(q0 + qq) * DIM + h * HD;
#pragma unroll
        for (int r = 0; r < 8; r++) {
            int dq = dq0 + r * 4;
            float4 v = *(const float4*)(src + dq * 4);
            Qs[(dq * 4 + 0) * 64 + qq] = v.x;
            Qs[(dq * 4 + 1) * 64 + qq] = v.y;
            Qs[(dq * 4 + 2) * 64 + qq] = v.z;
            Qs[(dq * 4 + 3) * 64 + qq] = v.w;
        }
    }
    if (tid < 64) {
        mrow[tid] = NEG_INF;
        lrow[tid] = 0.f;
    }

    u64 oacc[4][4];
#pragma unroll
    for (int i = 0; i < 4; i++)
#pragma unroll
        for (int j = 0; j < 4; j++) oacc[i][j] = 0ull;

    const int ntiles = qt + 1;
    for (int t = 0; t < ntiles; t++) {
        const int k0 = t * BKV;
        __syncthreads();

        {
            int kk = tid & 63;
            int dq0 = tid >> 6;
            const float* src = XK + (size_t)(k0 + kk) * KVD + kvh * HD;
#pragma unroll
            for (int r = 0; r < 8; r++) {
                int dq = dq0 + r * 4;
                float4 v = *(const float4*)(src + dq * 4);
                Ks[(dq * 4 + 0) * 64 + kk] = v.x;
                Ks[(dq * 4 + 1) * 64 + kk] = v.y;
                Ks[(dq * 4 + 2) * 64 + kk] = v.z;
                Ks[(dq * 4 + 3) * 64 + kk] = v.w;
            }
        }
        {
            int kk0 = tid >> 5;
            int dq = tid & 31;
            const float* src = XV + (size_t)kvh * HD + dq * 4;
#pragma unroll
            for (int r = 0; r < 8; r++) {
                int kk = kk0 + r * 8;
                float4 v = *(const float4*)(src + (size_t)(k0 + kk) * KVD);
                *(float4*)&Vs[kk * 128 + dq * 4] = v;
            }
        }
        __syncthreads();

        u64 sa[4][2];
#pragma unroll
        for (int i = 0; i < 4; i++) { sa[i][0] = 0ull; sa[i][1] = 0ull; }
#pragma unroll 8
        for (int d = 0; d < 128; d++) {
            float qv[4];
            *(float4*)qv = *(const float4*)&Qs[d * 64 + ty * 4];
            const u64* krow = (const u64*)&Ks[d * 64];
            u64 kp0 = krow[tx * 2];
            u64 kp1 = krow[tx * 2 + 1];
#pragma unroll
            for (int i = 0; i < 4; i++) {
                u64 qd = dup2(qv[i]);
                sa[i][0] = ffma2(qd, kp0, sa[i][0]);
                sa[i][1] = ffma2(qd, kp1, sa[i][1]);
            }
        }
        const float scale = 0.08838834764831845f;
#pragma unroll
        for (int i = 0; i < 4; i++) {
            float s[4];
            unpk2(sa[i][0], s[0], s[1]);
            unpk2(sa[i][1], s[2], s[3]);
            int qg = q0 + ty * 4 + i;
#pragma unroll
            for (int j = 0; j < 4; j++) {
                int kg = k0 + tx * 4 + j;
                float v = s[j] * scale;
                if (kg > qg) v = NEG_INF;
                Ss[(ty * 4 + i) * SPAD + tx * 4 + j] = v;
            }
        }
        __syncthreads();

#pragma unroll
        for (int rr = 0; rr < 8; rr++) {
            int r = warp * 8 + rr;
            float v1 = Ss[r * SPAD + lane];
            float v2 = Ss[r * SPAD + lane + 32];
            float mx = fmaxf(v1, v2);
#pragma unroll
            for (int off = 16; off; off >>= 1)
                mx = fmaxf(mx, __shfl_xor_sync(0xffffffffu, mx, off));
            float mold = mrow[r];
            float mnew = fmaxf(mold, mx);
            float p1 = __expf(v1 - mnew);
            float p2 = __expf(v2 - mnew);
            float s = p1 + p2;
#pragma unroll
            for (int off = 16; off; off >>= 1)
                s += __shfl_xor_sync(0xffffffffu, s, off);
            Ss[r * SPAD + lane] = p1;
            Ss[r * SPAD + lane + 32] = p2;
            if (lane == 0) {
                float f = __expf(mold - mnew);
                frow[r] = f;
                lrow[r] = lrow[r] * f + s;
                mrow[r] = mnew;
            }
        }
        __syncthreads();

#pragma unroll
        for (int i = 0; i < 4; i++) {
            u64 fd = dup2(frow[ty * 4 + i]);
#pragma unroll
            for (int j = 0; j < 4; j++) oacc[i][j] = fmul2(oacc[i][j], fd);
        }
#pragma unroll 4
        for (int kk = 0; kk < BKV; kk++) {
            float p[4];
#pragma unroll
            for (int i = 0; i < 4; i++) p[i] = Ss[(ty * 4 + i) * SPAD + kk];
            const u64* vrow = (const u64*)&Vs[kk * 128];
            u64 vp[4];
#pragma unroll
            for (int j = 0; j < 4; j++) vp[j] = vrow[tx * 4 + j];
#pragma unroll
            for (int i = 0; i < 4; i++) {
                u64 pd = dup2(p[i]);
#pragma unroll
                for (int j = 0; j < 4; j++) oacc[i][j] = ffma2(pd, vp[j], oacc[i][j]);
            }
        }
    }

#pragma unroll
    for (int i = 0; i < 4; i++) {
        int qg = q0 + ty * 4 + i;
        float rl = 1.0f / lrow[ty * 4 + i];
        float out[8];
#pragma unroll
        for (int j = 0; j < 4; j++) {
            float x, y;
            unpk2(oacc[i][j], x, y);
            out[2 * j] = x * rl;
            out[2 * j + 1] = y * rl;
        }
        float* dst = O + (size_t)qg * DIM + h * HD + tx * 8;
        *(float4*)dst = *(float4*)&out[0];
        *(float4*)(dst + 4) = *(float4*)&out[4];
    }
}

// ---------------- launch --------------------------------------------------------
extern "C" void kernel_launch(void* const* d_in, const int* in_sizes, int n_in,
                              void* d_out, int out_size) {
    const float* x  = (const float*)d_in[0];
    const float* wq = (const float*)d_in[1];
    const float* wk = (const float*)d_in[2];
    const float* wv = (const float*)d_in[3];
    const float* wo = (const float*)d_in[4];
    const float* fc = (const float*)d_in[5];
    const float* fs = (const float*)d_in[6];
    float* out = (float*)d_out;

    float *xq, *xk, *xv, *att;
    cudaGetSymbolAddress((void**)&xq, g_xq);
    cudaGetSymbolAddress((void**)&xk, g_xk);
    cudaGetSymbolAddress((void**)&xv, g_xv);
    cudaGetSymbolAddress((void**)&att, g_att);

    __nv_bfloat16 *xh, *xl, *ah, *al, *wqh, *wql, *wkh, *wkl, *wvh, *wvl, *woh, *wol;
    cudaGetSymbolAddress((void**)&xh, g_xh);
    cudaGetSymbolAddress((void**)&xl, g_xl);
    cudaGetSymbolAddress((void**)&ah, g_ah);
    cudaGetSymbolAddress((void**)&al, g_al);
    cudaGetSymbolAddress((void**)&wqh, g_wqh);
    cudaGetSymbolAddress((void**)&wql, g_wql);
    cudaGetSymbolAddress((void**)&wkh, g_wkh);
    cudaGetSymbolAddress((void**)&wkl, g_wkl);
    cudaGetSymbolAddress((void**)&wvh, g_wvh);
    cudaGetSymbolAddress((void**)&wvl, g_wvl);
    cudaGetSymbolAddress((void**)&woh, g_woh);
    cudaGetSymbolAddress((void**)&wol, g_wol);

    dim3 tsb(32, 8);
    transpose_split<<<dim3(DIM / 32, DIM / 32), tsb>>>(wq, wqh, wql, DIM, DIM);
    transpose_split<<<dim3(KVD / 32, DIM / 32), tsb>>>(wk, wkh, wkl, DIM, KVD);
    transpose_split<<<dim3(KVD / 32, DIM / 32), tsb>>>(wv, wvh, wvl, DIM, KVD);
    transpose_split<<<dim3(DIM / 32, DIM / 32), tsb>>>(wo, woh, wol, DIM, DIM);
    split_kernel<<<(SEQ * DIM + 255) / 256, 256>>>(x, xh, xl, SEQ * DIM);

    cudaFuncSetAttribute(gemm_hmma, cudaFuncAttributeMaxDynamicSharedMemorySize, SMEM_GEMM);
    gemm_hmma<<<dim3(DIM / BN, SEQ / BM), 256, SMEM_GEMM>>>(xh, xl, wqh, wql, xq, SEQ, DIM, DIM);
    gemm_hmma<<<dim3(KVD / BN, SEQ / BM), 256, SMEM_GEMM>>>(xh, xl, wkh, wkl, xk, SEQ, KVD, DIM);
    gemm_hmma<<<dim3(KVD / BN, SEQ / BM), 256, SMEM_GEMM>>>(xh, xl, wvh, wvl, xv, SEQ, KVD, DIM);

    rope_kernel<<<(SEQ * NH * 64 + 255) / 256, 256>>>(xq, fc, fs, NH);
    rope_kernel<<<(SEQ * NKV * 64 + 255) / 256, 256>>>(xk, fc, fs, NKV);

    int smem_bytes = (128 * 64 + 128 * 64 + 64 * 128 + 64 * SPAD + 3 * 64) * (int)sizeof(float);
    cudaFuncSetAttribute(attn_kernel, cudaFuncAttributeMaxDynamicSharedMemorySize, smem_bytes);
    attn_kernel<<<dim3(SEQ / BQ, NH), 256, smem_bytes>>>(xq, xk, xv, att);

    split_kernel<<<(SEQ * DIM + 255) / 256, 256>>>(att, ah, al, SEQ * DIM);
    gemm_hmma<<<dim3(DIM / BN, SEQ / BM), 256, SMEM_GEMM>>>(ah, al, woh, wol, out, SEQ, DIM, DIM);
}

// round 4
// speedup vs baseline: 2.9490x; 1.8672x over previous
#include <cuda_runtime.h>
#include <cuda_bf16.h>
#include <cstdint>

#define SEQ 2048
#define DIM 4096
#define NH 32
#define NKV 8
#define HD 128
#define KVD 1024   // NKV*HD

// ---------------- scratch (device globals) ----------------
__device__ float g_xq[SEQ * DIM];
__device__ float g_xk[SEQ * KVD];
__device__ float g_xv[SEQ * KVD];
__device__ float g_att[SEQ * DIM];

// bf16 hi/lo splits
__device__ __align__(128) __nv_bfloat16 g_xh[SEQ * DIM];
__device__ __align__(128) __nv_bfloat16 g_xl[SEQ * DIM];
__device__ __align__(128) __nv_bfloat16 g_ah[SEQ * DIM];
__device__ __align__(128) __nv_bfloat16 g_al[SEQ * DIM];
__device__ __align__(128) __nv_bfloat16 g_qh[SEQ * DIM];
__device__ __align__(128) __nv_bfloat16 g_ql[SEQ * DIM];
__device__ __align__(128) __nv_bfloat16 g_kh[SEQ * KVD];
__device__ __align__(128) __nv_bfloat16 g_kl[SEQ * KVD];
__device__ __align__(128) __nv_bfloat16 g_vh[SEQ * KVD];
__device__ __align__(128) __nv_bfloat16 g_vl[SEQ * KVD];
// transposed weights [N,K] bf16 hi/lo
__device__ __align__(128) __nv_bfloat16 g_wqh[DIM * DIM];
__device__ __align__(128) __nv_bfloat16 g_wql[DIM * DIM];
__device__ __align__(128) __nv_bfloat16 g_wkh[KVD * DIM];
__device__ __align__(128) __nv_bfloat16 g_wkl[KVD * DIM];
__device__ __align__(128) __nv_bfloat16 g_wvh[KVD * DIM];
__device__ __align__(128) __nv_bfloat16 g_wvl[KVD * DIM];
__device__ __align__(128) __nv_bfloat16 g_woh[DIM * DIM];
__device__ __align__(128) __nv_bfloat16 g_wol[DIM * DIM];

// ---------------- PTX helpers (baseline-PTX, sm_80-class) ----------------
__device__ __forceinline__ uint32_t smem_u32(const void* p) {
    uint32_t a;
    asm("{ .reg .u64 t; cvta.to.shared.u64 t, %1; cvt.u32.u64 %0, t; }" : "=r"(a) : "l"(p));
    return a;
}
__device__ __forceinline__ void cpa16(uint32_t s, const void* g) {
    asm volatile("cp.async.cg.shared.global [%0], [%1], 16;" :: "r"(s), "l"(g));
}
__device__ __forceinline__ void ldsm4(unsigned* r, uint32_t addr) {
    asm volatile("ldmatrix.sync.aligned.m8n8.x4.shared.b16 {%0,%1,%2,%3}, [%4];"
                 : "=r"(r[0]), "=r"(r[1]), "=r"(r[2]), "=r"(r[3]) : "r"(addr));
}
__device__ __forceinline__ void ldsm2(unsigned* r, uint32_t addr) {
    asm volatile("ldmatrix.sync.aligned.m8n8.x2.shared.b16 {%0,%1}, [%2];"
                 : "=r"(r[0]), "=r"(r[1]) : "r"(addr));
}
__device__ __forceinline__ void ldsm2t(unsigned* r, uint32_t addr) {
    asm volatile("ldmatrix.sync.aligned.m8n8.x2.trans.shared.b16 {%0,%1}, [%2];"
                 : "=r"(r[0]), "=r"(r[1]) : "r"(addr));
}
__device__ __forceinline__ void mma16816(float* d, const unsigned* a, const unsigned* b) {
    asm volatile(
        "mma.sync.aligned.m16n8k16.row.col.f32.bf16.bf16.f32 "
        "{%0,%1,%2,%3}, {%4,%5,%6,%7}, {%8,%9}, {%0,%1,%2,%3};"
        : "+f"(d[0]), "+f"(d[1]), "+f"(d[2]), "+f"(d[3])
        : "r"(a[0]), "r"(a[1]), "r"(a[2]), "r"(a[3]), "r"(b[0]), "r"(b[1]));
}
// pack two f32 -> bf16x2 (lo in low half)
__device__ __forceinline__ unsigned pack_bf2(float lo, float hi) {
    unsigned d;
    asm("cvt.rn.bf16x2.f32 %0, %1, %2;" : "=r"(d) : "f"(hi), "f"(lo));
    return d;
}
__device__ __forceinline__ float bf2lo(unsigned r) { return __uint_as_float(r << 16); }
__device__ __forceinline__ float bf2hi(unsigned r) { return __uint_as_float(r & 0xffff0000u); }

// ---------------- conversion kernels ----------------
__global__ void split_kernel(const float* __restrict__ x, __nv_bfloat16* __restrict__ h,
                             __nv_bfloat16* __restrict__ l, int n) {
    int i = blockIdx.x * blockDim.x + threadIdx.x;
    if (i >= n) return;
    float v = x[i];
    __nv_bfloat16 hi = __float2bfloat16(v);
    __nv_bfloat16 lo = __float2bfloat16(v - __bfloat162float(hi));
    h[i] = hi;
    l[i] = lo;
}

// w [K,N] f32 -> out [N,K] bf16 hi/lo
__global__ void transpose_split(const float* __restrict__ w, __nv_bfloat16* __restrict__ th,
                                __nv_bfloat16* __restrict__ tl, int K, int N) {
    __shared__ float tile[32][33];
    int k0 = blockIdx.y * 32, n0 = blockIdx.x * 32;
    int tx = threadIdx.x, ty = threadIdx.y;   // 32 x 8
#pragma unroll
    for (int r = 0; r < 4; r++)
        tile[ty + r * 8][tx] = w[(size_t)(k0 + ty + r * 8) * N + n0 + tx];
    __syncthreads();
#pragma unroll
    for (int r = 0; r < 4; r++) {
        float v = tile[tx][ty + r * 8];
        __nv_bfloat16 hi = __float2bfloat16(v);
        __nv_bfloat16 lo = __float2bfloat16(v - __bfloat162float(hi));
        size_t o = (size_t)(n0 + ty + r * 8) * K + k0 + tx;
        th[o] = hi;
        tl[o] = lo;
    }
}

// ---------------- HMMA bf16x3 GEMM v2: C[M,N] = A[M,K] @ B[N,K]^T ----------------
// CTA 128x128, 4 warps, warp tile 64x64, BK=32, double-buffered cp.async.
#define BM 128
#define BN 128
#define BK 32
#define LDE 40                     // padded bf16/row (80B: conflict-free LDSM)
#define ARR (128 * LDE * 2)        // 10240 B
#define STG (4 * ARR)              // 40960 B per stage
#define SMEM_GEMM (2 * STG)        // 81920 B

__global__ __launch_bounds__(128, 2)
void gemm_hmma(const __nv_bfloat16* __restrict__ Ah, const __nv_bfloat16* __restrict__ Al,
               const __nv_bfloat16* __restrict__ Bh, const __nv_bfloat16* __restrict__ Bl,
               float* __restrict__ C, int M, int N, int K) {
    extern __shared__ char smem[];
    const uint32_t sb = smem_u32(smem);
    const int tid = threadIdx.x;
    const int lane = tid & 31, warp = tid >> 5;
    const int m0 = blockIdx.y * BM, n0 = blockIdx.x * BN;
    const int wm = (warp & 1) * 64, wn = (warp >> 1) * 64;

    float acc[4][8][4];
#pragma unroll
    for (int m = 0; m < 4; m++)
#pragma unroll
        for (int j = 0; j < 8; j++)
#pragma unroll
            for (int v = 0; v < 4; v++) acc[m][j][v] = 0.f;

    auto load_stage = [&](int buf, int ko) {
        uint32_t s0 = sb + buf * STG;
#pragma unroll
        for (int s = tid; s < 512; s += 128) {
            int row = s >> 2, c = s & 3;
            uint32_t so = s0 + (uint32_t)row * (LDE * 2) + c * 16;
            size_t go = (size_t)row * K + ko + c * 8;
            cpa16(so, Ah + (size_t)m0 * K + go);
            cpa16(so + ARR, Al + (size_t)m0 * K + go);
            cpa16(so + 2 * ARR, Bh + (size_t)n0 * K + go);
            cpa16(so + 3 * ARR, Bl + (size_t)n0 * K + go);
        }
        asm volatile("cp.async.commit_group;");
    };

    load_stage(0, 0);
    const int NS = K / BK;
#pragma unroll 1
    for (int s = 0; s < NS; s++) {
        if (s + 1 < NS) {
            load_stage((s + 1) & 1, (s + 1) * BK);
            asm volatile("cp.async.wait_group 1;");
        } else {
            asm volatile("cp.async.wait_group 0;");
        }
        __syncthreads();

        const uint32_t base = sb + (s & 1) * STG;
#pragma unroll
        for (int ks = 0; ks < 2; ks++) {
            const int k0 = ks * 16;
            unsigned ah[4][4], al[4][4];
#pragma unroll
            for (int m = 0; m < 4; m++) {
                uint32_t aa = base +
                    (uint32_t)(wm + m * 16 + (lane & 15)) * (LDE * 2) +
                    (uint32_t)(k0 + (lane >> 4) * 8) * 2;
                ldsm4(ah[m], aa);
                ldsm4(al[m], aa + ARR);
            }
#pragma unroll
            for (int j = 0; j < 8; j++) {
                uint32_t ba = base + 2 * ARR +
                    (uint32_t)(wn + j * 8 + (lane & 7)) * (LDE * 2) +
                    (uint32_t)(k0 + ((lane >> 3) & 1) * 8) * 2;
                unsigned bh[2], bl[2];
                ldsm2(bh, ba);
                ldsm2(bl, ba + ARR);
#pragma unroll
                for (int m = 0; m < 4; m++) {
                    mma16816(acc[m][j], ah[m], bh);
                    mma16816(acc[m][j], ah[m], bl);
                    mma16816(acc[m][j], al[m], bh);
                }
            }
        }
        __syncthreads();
    }

#pragma unroll
    for (int m = 0; m < 4; m++) {
        int r0 = m0 + wm + m * 16 + (lane >> 2);
#pragma unroll
        for (int j = 0; j < 8; j++) {
            int c = n0 + wn + j * 8 + (lane & 3) * 2;
            *(float2*)(C + (size_t)r0 * N + c) = make_float2(acc[m][j][0], acc[m][j][1]);
            *(float2*)(C + (size_t)(r0 + 8) * N + c) = make_float2(acc[m][j][2], acc[m][j][3]);
        }
    }
}

// ---------------- RoPE ----------------
__global__ void rope_kernel(float* __restrict__ x, const float* __restrict__ cs,
                            const float* __restrict__ sn, int nheads) {
    int idx = blockIdx.x * blockDim.x + threadIdx.x;
    int total = SEQ * nheads * (HD / 2);
    if (idx >= total) return;
    int i = idx & 63;
    int t = idx >> 6;
    int h = t % nheads;
    int pos = t / nheads;
    float c = cs[pos * 64 + i];
    float s = sn[pos * 64 + i];
    float2* p = (float2*)(x + (size_t)(pos * nheads + h) * HD) + i;
    float2 v = *p;
    float2 o;
    o.x = v.x * c - v.y * s;
    o.y = v.x * s + v.y * c;
    *p = o;
}

// ---------------- tensorized flash attention ----------------
// CTA: 128 q-rows x 1 head; 8 warps, each owns 16 q-rows. KV tiles of 64,
// double-buffered. bf16x3 for QK^T and PV; P split in registers.
#define AQ 128
#define AKV 64
#define LDA 136                    // bf16 per row (272 B)
#define QARR (128 * LDA * 2)       // 34816 B
#define KARR (64 * LDA * 2)        // 17408 B
#define KVSTG (4 * KARR)           // 69632 B (Kh,Kl,Vh,Vl)
#define SMEM_ATT (2 * QARR + 2 * KVSTG)   // 208896 B

__global__ __launch_bounds__(256, 1)
void attn_mma(const __nv_bfloat16* __restrict__ Qh, const __nv_bfloat16* __restrict__ Ql,
              const __nv_bfloat16* __restrict__ Kh, const __nv_bfloat16* __restrict__ Kl,
              const __nv_bfloat16* __restrict__ Vh, const __nv_bfloat16* __restrict__ Vl,
              float* __restrict__ O) {
    extern __shared__ char smem[];
    const uint32_t sb = smem_u32(smem);
    const int tid = threadIdx.x;
    const int lane = tid & 31, warp = tid >> 5;
    const int h = blockIdx.y;
    const int qt = (gridDim.x - 1) - blockIdx.x;   // long tiles first
    const int q0 = qt * AQ;
    const int kvh = h >> 2;
    const float scale = 0.08838834764831845f;      // 1/sqrt(128)
    const float NEGF = -1e30f;

    // ---- Q tile load (128 rows x 256B, hi+lo), group 0 together with KV(0)
#pragma unroll
    for (int s = tid; s < 128 * 16; s += 256) {
        int row = s >> 4, c = s & 15;
        uint32_t so = sb + (uint32_t)row * (LDA * 2) + c * 16;
        size_t go = (size_t)(q0 + row) * DIM + h * HD + c * 8;
        cpa16(so, Qh + go);
        cpa16(so + QARR, Ql + go);
    }
    auto load_kv = [&](int buf, int k0) {
        uint32_t b0 = sb + 2 * QARR + buf * KVSTG;
#pragma unroll
        for (int s = tid; s < 1024; s += 256) {
            int row = s >> 4, c = s & 15;
            uint32_t so = b0 + (uint32_t)row * (LDA * 2) + c * 16;
            size_t go = (size_t)(k0 + row) * KVD + kvh * HD + c * 8;
            cpa16(so, Kh + go);
            cpa16(so + KARR, Kl + go);
            cpa16(so + 2 * KARR, Vh + go);
            cpa16(so + 3 * KARR, Vl + go);
        }
        asm volatile("cp.async.commit_group;");
    };
    load_kv(0, 0);

    // per-thread softmax state: rows rA = q0+warp*16+(lane>>2), rB = rA+8
    const int rA = q0 + warp * 16 + (lane >> 2);
    const int qwmax = q0 + warp * 16 + 15;
    float mA = NEGF, mB = NEGF, lA = 0.f, lB = 0.f;
    float o[16][4];
#pragma unroll
    for (int j = 0; j < 16; j++)
#pragma unroll
        for (int v = 0; v < 4; v++) o[j][v] = 0.f;

    const int ntiles = (q0 + AQ) / AKV;
#pragma unroll 1
    for (int t = 0; t < ntiles; t++) {
        const int k0 = t * AKV;
        if (t + 1 < ntiles) {
            load_kv((t + 1) & 1, (t + 1) * AKV);
            asm volatile("cp.async.wait_group 1;");
        } else {
            asm volatile("cp.async.wait_group 0;");
        }
        __syncthreads();

        if (k0 <= qwmax) {   // warp has at least one unmasked row in this tile
            const uint32_t kb = sb + 2 * QARR + (t & 1) * KVSTG;
            const uint32_t vb = kb + 2 * KARR;

            // ---- S = Q K^T (bf16x3), warp tile 16 x 64
            float s[8][4];
#pragma unroll
            for (int j = 0; j < 8; j++)
#pragma unroll
                for (int v = 0; v < 4; v++) s[j][v] = 0.f;

#pragma unroll
            for (int kc = 0; kc < 8; kc++) {
                uint32_t qa = sb + (uint32_t)(warp * 16 + (lane & 15)) * (LDA * 2) +
                              (uint32_t)(kc * 16 + (lane >> 4) * 8) * 2;
                unsigned aqh[4], aql[4];
                ldsm4(aqh, qa);
                ldsm4(aql, qa + QARR);
#pragma unroll
                for (int j = 0; j < 8; j++) {
                    uint32_t ka = kb + (uint32_t)(j * 8 + (lane & 7)) * (LDA * 2) +
                                  (uint32_t)(kc * 16 + ((lane >> 3) & 1) * 8) * 2;
                    unsigned bkh[2], bkl[2];
                    ldsm2(bkh, ka);
                    ldsm2(bkl, ka + KARR);
                    mma16816(s[j], aqh, bkh);
                    mma16816(s[j], aqh, bkl);
                    mma16816(s[j], aql, bkh);
                }
            }

            // ---- scale + causal mask
            const bool need_mask = (k0 + AKV - 1) > (q0 + warp * 16);
#pragma unroll
            for (int j = 0; j < 8; j++) {
#pragma unroll
                for (int v = 0; v < 4; v++) s[j][v] *= scale;
                if (need_mask) {
                    int cg = k0 + j * 8 + (lane & 3) * 2;
                    if (cg > rA) s[j][0] = NEGF;
                    if (cg + 1 > rA) s[j][1] = NEGF;
                    if (cg > rA + 8) s[j][2] = NEGF;
                    if (cg + 1 > rA + 8) s[j][3] = NEGF;
                }
            }

            // ---- online softmax (rows spread over quad lanes)
            float mxA = NEGF, mxB = NEGF;
#pragma unroll
            for (int j = 0; j < 8; j++) {
                mxA = fmaxf(mxA, fmaxf(s[j][0], s[j][1]));
                mxB = fmaxf(mxB, fmaxf(s[j][2], s[j][3]));
            }
            mxA = fmaxf(mxA, __shfl_xor_sync(0xffffffffu, mxA, 1));
            mxA = fmaxf(mxA, __shfl_xor_sync(0xffffffffu, mxA, 2));
            mxB = fmaxf(mxB, __shfl_xor_sync(0xffffffffu, mxB, 1));
            mxB = fmaxf(mxB, __shfl_xor_sync(0xffffffffu, mxB, 2));
            float mAn = fmaxf(mA, mxA), mBn = fmaxf(mB, mxB);
            float fA = __expf(mA - mAn), fB = __expf(mB - mBn);
            float sA = 0.f, sB = 0.f;
#pragma unroll
            for (int j = 0; j < 8; j++) {
                s[j][0] = __expf(s[j][0] - mAn);
                s[j][1] = __expf(s[j][1] - mAn);
                s[j][2] = __expf(s[j][2] - mBn);
                s[j][3] = __expf(s[j][3] - mBn);
                sA += s[j][0] + s[j][1];
                sB += s[j][2] + s[j][3];
            }
            sA += __shfl_xor_sync(0xffffffffu, sA, 1);
            sA += __shfl_xor_sync(0xffffffffu, sA, 2);
            sB += __shfl_xor_sync(0xffffffffu, sB, 1);
            sB += __shfl_xor_sync(0xffffffffu, sB, 2);
            lA = lA * fA + sA;
            lB = lB * fB + sB;
            mA = mAn;
            mB = mBn;
#pragma unroll
            for (int j = 0; j < 16; j++) {
                o[j][0] *= fA;
                o[j][1] *= fA;
                o[j][2] *= fB;
                o[j][3] *= fB;
            }

            // ---- O += P V (bf16x3; P split in registers, V^T via ldmatrix.trans)
#pragma unroll
            for (int kc = 0; kc < 4; kc++) {
                const int j0 = 2 * kc, j1 = 2 * kc + 1;
                unsigned ph[4], pl[4];
                ph[0] = pack_bf2(s[j0][0], s[j0][1]);
                ph[1] = pack_bf2(s[j0][2], s[j0][3]);
                ph[2] = pack_bf2(s[j1][0], s[j1][1]);
                ph[3] = pack_bf2(s[j1][2], s[j1][3]);
                pl[0] = pack_bf2(s[j0][0] - bf2lo(ph[0]), s[j0][1] - bf2hi(ph[0]));
                pl[1] = pack_bf2(s[j0][2] - bf2lo(ph[1]), s[j0][3] - bf2hi(ph[1]));
                pl[2] = pack_bf2(s[j1][0] - bf2lo(ph[2]), s[j1][1] - bf2hi(ph[2]));
                pl[3] = pack_bf2(s[j1][2] - bf2lo(ph[3]), s[j1][3] - bf2hi(ph[3]));
#pragma unroll
                for (int j = 0; j < 16; j++) {
                    uint32_t va = vb + (uint32_t)(kc * 16 + (lane & 15)) * (LDA * 2) +
                                  (uint32_t)(j * 8) * 2;
                    unsigned bvh[2], bvl[2];
                    ldsm2t(bvh, va);
                    ldsm2t(bvl, va + KARR);
                    mma16816(o[j], ph, bvh);
                    mma16816(o[j], ph, bvl);
                    mma16816(o[j], pl, bvh);
                }
            }
        }
        __syncthreads();
    }

    // ---- epilogue: normalize, write f32
    float rlA = 1.0f / lA, rlB = 1.0f / lB;
#pragma unroll
    for (int j = 0; j < 16; j++) {
        int c = h * HD + j * 8 + (lane & 3) * 2;
        *(float2*)(O + (size_t)rA * DIM + c) = make_float2(o[j][0] * rlA, o[j][1] * rlA);
        *(float2*)(O + (size_t)(rA + 8) * DIM + c) = make_float2(o[j][2] * rlB, o[j][3] * rlB);
    }
}

// ---------------- launch --------------------------------------------------------
extern "C" void kernel_launch(void* const* d_in, const int* in_sizes, int n_in,
                              void* d_out, int out_size) {
    const float* x  = (const float*)d_in[0];
    const float* wq = (const float*)d_in[1];
    const float* wk = (const float*)d_in[2];
    const float* wv = (const float*)d_in[3];
    const float* wo = (const float*)d_in[4];
    const float* fc = (const float*)d_in[5];
    const float* fs = (const float*)d_in[6];
    float* out = (float*)d_out;

    float *xq, *xk, *xv, *att;
    cudaGetSymbolAddress((void**)&xq, g_xq);
    cudaGetSymbolAddress((void**)&xk, g_xk);
    cudaGetSymbolAddress((void**)&xv, g_xv);
    cudaGetSymbolAddress((void**)&att, g_att);

    __nv_bfloat16 *xh, *xl, *ah, *al, *qh, *ql, *kh, *kl, *vh, *vl;
    __nv_bfloat16 *wqh, *wql, *wkh, *wkl, *wvh, *wvl, *woh, *wol;
    cudaGetSymbolAddress((void**)&xh, g_xh);
    cudaGetSymbolAddress((void**)&xl, g_xl);
    cudaGetSymbolAddress((void**)&ah, g_ah);
    cudaGetSymbolAddress((void**)&al, g_al);
    cudaGetSymbolAddress((void**)&qh, g_qh);
    cudaGetSymbolAddress((void**)&ql, g_ql);
    cudaGetSymbolAddress((void**)&kh, g_kh);
    cudaGetSymbolAddress((void**)&kl, g_kl);
    cudaGetSymbolAddress((void**)&vh, g_vh);
    cudaGetSymbolAddress((void**)&vl, g_vl);
    cudaGetSymbolAddress((void**)&wqh, g_wqh);
    cudaGetSymbolAddress((void**)&wql, g_wql);
    cudaGetSymbolAddress((void**)&wkh, g_wkh);
    cudaGetSymbolAddress((void**)&wkl, g_wkl);
    cudaGetSymbolAddress((void**)&wvh, g_wvh);
    cudaGetSymbolAddress((void**)&wvl, g_wvl);
    cudaGetSymbolAddress((void**)&woh, g_woh);
    cudaGetSymbolAddress((void**)&wol, g_wol);

    dim3 tsb(32, 8);
    transpose_split<<<dim3(DIM / 32, DIM / 32), tsb>>>(wq, wqh, wql, DIM, DIM);
    transpose_split<<<dim3(KVD / 32, DIM / 32), tsb>>>(wk, wkh, wkl, DIM, KVD);
    transpose_split<<<dim3(KVD / 32, DIM / 32), tsb>>>(wv, wvh, wvl, DIM, KVD);
    transpose_split<<<dim3(DIM / 32, DIM / 32), tsb>>>(wo, woh, wol, DIM, DIM);
    split_kernel<<<(SEQ * DIM + 255) / 256, 256>>>(x, xh, xl, SEQ * DIM);

    cudaFuncSetAttribute(gemm_hmma, cudaFuncAttributeMaxDynamicSharedMemorySize, SMEM_GEMM);
    gemm_hmma<<<dim3(DIM / BN, SEQ / BM), 128, SMEM_GEMM>>>(xh, xl, wqh, wql, xq, SEQ, DIM, DIM);
    gemm_hmma<<<dim3(KVD / BN, SEQ / BM), 128, SMEM_GEMM>>>(xh, xl, wkh, wkl, xk, SEQ, KVD, DIM);
    gemm_hmma<<<dim3(KVD / BN, SEQ / BM), 128, SMEM_GEMM>>>(xh, xl, wvh, wvl, xv, SEQ, KVD, DIM);

    rope_kernel<<<(SEQ * NH * 64 + 255) / 256, 256>>>(xq, fc, fs, NH);
    rope_kernel<<<(SEQ * NKV * 64 + 255) / 256, 256>>>(xk, fc, fs, NKV);

    split_kernel<<<(SEQ * DIM + 255) / 256, 256>>>(xq, qh, ql, SEQ * DIM);
    split_kernel<<<(SEQ * KVD + 255) / 256, 256>>>(xk, kh, kl, SEQ * KVD);
    split_kernel<<<(SEQ * KVD + 255) / 256, 256>>>(xv, vh, vl, SEQ * KVD);

    cudaFuncSetAttribute(attn_mma, cudaFuncAttributeMaxDynamicSharedMemorySize, SMEM_ATT);
    attn_mma<<<dim3(SEQ / AQ, NH), 256, SMEM_ATT>>>(qh, ql, kh, kl, vh, vl, att);

    split_kernel<<<(SEQ * DIM + 255) / 256, 256>>>(att, ah, al, SEQ * DIM);
    gemm_hmma<<<dim3(DIM / BN, SEQ / BM), 128, SMEM_GEMM>>>(ah, al, woh, wol, out, SEQ, DIM, DIM);
}

// round 5
// speedup vs baseline: 3.2353x; 1.0971x over previous
#include <cuda_runtime.h>
#include <cuda_bf16.h>
#include <cstdint>

#define SEQ 2048
#define DIM 4096
#define NH 32
#define NKV 8
#define HD 128
#define KVD 1024   // NKV*HD
#define NQKV 6144  // DIM + 2*KVD

// ---------------- scratch (device globals) ----------------
__device__ float g_xqkv[SEQ * NQKV];

__device__ __align__(128) __nv_bfloat16 g_xh[SEQ * DIM];
__device__ __align__(128) __nv_bfloat16 g_xl[SEQ * DIM];
__device__ __align__(128) __nv_bfloat16 g_ah[SEQ * DIM];
__device__ __align__(128) __nv_bfloat16 g_al[SEQ * DIM];
__device__ __align__(128) __nv_bfloat16 g_qh[SEQ * DIM];
__device__ __align__(128) __nv_bfloat16 g_ql[SEQ * DIM];
__device__ __align__(128) __nv_bfloat16 g_kh[SEQ * KVD];
__device__ __align__(128) __nv_bfloat16 g_kl[SEQ * KVD];
__device__ __align__(128) __nv_bfloat16 g_vh[SEQ * KVD];
__device__ __align__(128) __nv_bfloat16 g_vl[SEQ * KVD];
// merged transposed QKV weights [NQKV, DIM] bf16 hi/lo + wo
__device__ __align__(128) __nv_bfloat16 g_wh[NQKV * DIM];
__device__ __align__(128) __nv_bfloat16 g_wl[NQKV * DIM];
__device__ __align__(128) __nv_bfloat16 g_woh[DIM * DIM];
__device__ __align__(128) __nv_bfloat16 g_wol[DIM * DIM];

// ---------------- PTX helpers (baseline-PTX, sm_80-class) ----------------
__device__ __forceinline__ uint32_t smem_u32(const void* p) {
    uint32_t a;
    asm("{ .reg .u64 t; cvta.to.shared.u64 t, %1; cvt.u32.u64 %0, t; }" : "=r"(a) : "l"(p));
    return a;
}
__device__ __forceinline__ void cpa16(uint32_t s, const void* g) {
    asm volatile("cp.async.cg.shared.global [%0], [%1], 16;" :: "r"(s), "l"(g));
}
__device__ __forceinline__ void ldsm4(unsigned* r, uint32_t addr) {
    asm volatile("ldmatrix.sync.aligned.m8n8.x4.shared.b16 {%0,%1,%2,%3}, [%4];"
                 : "=r"(r[0]), "=r"(r[1]), "=r"(r[2]), "=r"(r[3]) : "r"(addr));
}
__device__ __forceinline__ void ldsm2(unsigned* r, uint32_t addr) {
    asm volatile("ldmatrix.sync.aligned.m8n8.x2.shared.b16 {%0,%1}, [%2];"
                 : "=r"(r[0]), "=r"(r[1]) : "r"(addr));
}
__device__ __forceinline__ void ldsm2t(unsigned* r, uint32_t addr) {
    asm volatile("ldmatrix.sync.aligned.m8n8.x2.trans.shared.b16 {%0,%1}, [%2];"
                 : "=r"(r[0]), "=r"(r[1]) : "r"(addr));
}
__device__ __forceinline__ void mma16816(float* d, const unsigned* a, const unsigned* b) {
    asm volatile(
        "mma.sync.aligned.m16n8k16.row.col.f32.bf16.bf16.f32 "
        "{%0,%1,%2,%3}, {%4,%5,%6,%7}, {%8,%9}, {%0,%1,%2,%3};"
        : "+f"(d[0]), "+f"(d[1]), "+f"(d[2]), "+f"(d[3])
        : "r"(a[0]), "r"(a[1]), "r"(a[2]), "r"(a[3]), "r"(b[0]), "r"(b[1]));
}
__device__ __forceinline__ unsigned pack_bf2(float lo, float hi) {
    unsigned d;
    asm("cvt.rn.bf16x2.f32 %0, %1, %2;" : "=r"(d) : "f"(hi), "f"(lo));
    return d;
}
__device__ __forceinline__ float bf2lo(unsigned r) { return __uint_as_float(r << 16); }
__device__ __forceinline__ float bf2hi(unsigned r) { return __uint_as_float(r & 0xffff0000u); }

// ---------------- conversion kernels ----------------
__global__ void split_kernel(const float* __restrict__ x, __nv_bfloat16* __restrict__ h,
                             __nv_bfloat16* __restrict__ l, int n) {
    int i = blockIdx.x * blockDim.x + threadIdx.x;
    if (i >= n) return;
    float v = x[i];
    __nv_bfloat16 hi = __float2bfloat16(v);
    __nv_bfloat16 lo = __float2bfloat16(v - __bfloat162float(hi));
    h[i] = hi;
    l[i] = lo;
}

// merged QKV weight transpose+split: out[n, k] for n in [0,6144)
__global__ void transpose_split_qkv(const float* __restrict__ wq, const float* __restrict__ wk,
                                    const float* __restrict__ wv,
                                    __nv_bfloat16* __restrict__ th, __nv_bfloat16* __restrict__ tl) {
    __shared__ float tile[32][33];
    int k0 = blockIdx.y * 32, n0 = blockIdx.x * 32;
    int tx = threadIdx.x, ty = threadIdx.y;   // 32 x 8
    const float* src;
    int nn0, ldn;
    if (n0 < DIM) { src = wq; nn0 = n0; ldn = DIM; }
    else if (n0 < DIM + KVD) { src = wk; nn0 = n0 - DIM; ldn = KVD; }
    else { src = wv; nn0 = n0 - DIM - KVD; ldn = KVD; }
#pragma unroll
    for (int r = 0; r < 4; r++)
        tile[ty + r * 8][tx] = src[(size_t)(k0 + ty + r * 8) * ldn + nn0 + tx];
    __syncthreads();
#pragma unroll
    for (int r = 0; r < 4; r++) {
        float v = tile[tx][ty + r * 8];
        __nv_bfloat16 hi = __float2bfloat16(v);
        __nv_bfloat16 lo = __float2bfloat16(v - __bfloat162float(hi));
        size_t o = (size_t)(n0 + ty + r * 8) * DIM + k0 + tx;
        th[o] = hi;
        tl[o] = lo;
    }
}

// wo [K,N] f32 -> [N,K] bf16 hi/lo
__global__ void transpose_split(const float* __restrict__ w, __nv_bfloat16* __restrict__ th,
                                __nv_bfloat16* __restrict__ tl, int K, int N) {
    __shared__ float tile[32][33];
    int k0 = blockIdx.y * 32, n0 = blockIdx.x * 32;
    int tx = threadIdx.x, ty = threadIdx.y;
#pragma unroll
    for (int r = 0; r < 4; r++)
        tile[ty + r * 8][tx] = w[(size_t)(k0 + ty + r * 8) * N + n0 + tx];
    __syncthreads();
#pragma unroll
    for (int r = 0; r < 4; r++) {
        float v = tile[tx][ty + r * 8];
        __nv_bfloat16 hi = __float2bfloat16(v);
        __nv_bfloat16 lo = __float2bfloat16(v - __bfloat162float(hi));
        size_t o = (size_t)(n0 + ty + r * 8) * K + k0 + tx;
        th[o] = hi;
        tl[o] = lo;
    }
}

// fused RoPE + hi/lo split of the merged QKV projection output
// one thread per (pos, float-pair); pairs per row = NQKV/2 = 3072
__global__ void postproc_kernel(const float* __restrict__ xqkv,
                                const float* __restrict__ cs, const float* __restrict__ sn,
                                __nv_bfloat16* __restrict__ qh, __nv_bfloat16* __restrict__ ql,
                                __nv_bfloat16* __restrict__ kh, __nv_bfloat16* __restrict__ kl,
                                __nv_bfloat16* __restrict__ vh, __nv_bfloat16* __restrict__ vl) {
    int idx = blockIdx.x * blockDim.x + threadIdx.x;
    if (idx >= SEQ * 3072) return;
    int pos = idx / 3072;
    int p = idx - pos * 3072;

    const float* row = xqkv + (size_t)pos * NQKV;
    float a, b;
    __nv_bfloat16 *bh, *bl;
    size_t oofs;
    if (p < 2048) {            // Q: head h = p>>6, pair i = p&63
        int i = p & 63;
        float2 v = *(const float2*)(row + 2 * p);
        float c = cs[pos * 64 + i], s = sn[pos * 64 + i];
        a = v.x * c - v.y * s;
        b = v.x * s + v.y * c;
        bh = qh; bl = ql;
        oofs = (size_t)pos * DIM + 2 * p;
    } else if (p < 2560) {     // K
        int pk = p - 2048;
        int i = pk & 63;
        float2 v = *(const float2*)(row + DIM + 2 * pk);
        float c = cs[pos * 64 + i], s = sn[pos * 64 + i];
        a = v.x * c - v.y * s;
        b = v.x * s + v.y * c;
        bh = kh; bl = kl;
        oofs = (size_t)pos * KVD + 2 * pk;
    } else {                   // V (no rope)
        int pv = p - 2560;
        float2 v = *(const float2*)(row + DIM + KVD + 2 * pv);
        a = v.x;
        b = v.y;
        bh = vh; bl = vl;
        oofs = (size_t)pos * KVD + 2 * pv;
    }
    unsigned hi = pack_bf2(a, b);
    unsigned lo = pack_bf2(a - bf2lo(hi), b - bf2hi(hi));
    *(unsigned*)(bh + oofs) = hi;
    *(unsigned*)(bl + oofs) = lo;
}

// ---------------- HMMA bf16x3 GEMM: C[M,N] = A[M,K] @ B[N,K]^T ----------------
#define BM 128
#define BN 128
#define BK 32
#define LDE 40
#define ARR (128 * LDE * 2)        // 10240 B
#define STG (4 * ARR)              // 40960 B
#define SMEM_GEMM (2 * STG)        // 81920 B

__global__ __launch_bounds__(128, 2)
void gemm_hmma(const __nv_bfloat16* __restrict__ Ah, const __nv_bfloat16* __restrict__ Al,
               const __nv_bfloat16* __restrict__ Bh, const __nv_bfloat16* __restrict__ Bl,
               float* __restrict__ C, int M, int N, int K) {
    extern __shared__ char smem[];
    const uint32_t sb = smem_u32(smem);
    const int tid = threadIdx.x;
    const int lane = tid & 31, warp = tid >> 5;
    const int m0 = blockIdx.y * BM, n0 = blockIdx.x * BN;
    const int wm = (warp & 1) * 64, wn = (warp >> 1) * 64;

    float acc[4][8][4];
#pragma unroll
    for (int m = 0; m < 4; m++)
#pragma unroll
        for (int j = 0; j < 8; j++)
#pragma unroll
            for (int v = 0; v < 4; v++) acc[m][j][v] = 0.f;

    auto load_stage = [&](int buf, int ko) {
        uint32_t s0 = sb + buf * STG;
#pragma unroll
        for (int s = tid; s < 512; s += 128) {
            int row = s >> 2, c = s & 3;
            uint32_t so = s0 + (uint32_t)row * (LDE * 2) + c * 16;
            size_t go = (size_t)row * K + ko + c * 8;
            cpa16(so, Ah + (size_t)m0 * K + go);
            cpa16(so + ARR, Al + (size_t)m0 * K + go);
            cpa16(so + 2 * ARR, Bh + (size_t)n0 * K + go);
            cpa16(so + 3 * ARR, Bl + (size_t)n0 * K + go);
        }
        asm volatile("cp.async.commit_group;");
    };

    load_stage(0, 0);
    const int NS = K / BK;
#pragma unroll 1
    for (int s = 0; s < NS; s++) {
        if (s + 1 < NS) {
            load_stage((s + 1) & 1, (s + 1) * BK);
            asm volatile("cp.async.wait_group 1;");
        } else {
            asm volatile("cp.async.wait_group 0;");
        }
        __syncthreads();

        const uint32_t base = sb + (s & 1) * STG;
#pragma unroll
        for (int ks = 0; ks < 2; ks++) {
            const int k0 = ks * 16;
            unsigned ah[4][4], al[4][4];
#pragma unroll
            for (int m = 0; m < 4; m++) {
                uint32_t aa = base +
                    (uint32_t)(wm + m * 16 + (lane & 15)) * (LDE * 2) +
                    (uint32_t)(k0 + (lane >> 4) * 8) * 2;
                ldsm4(ah[m], aa);
                ldsm4(al[m], aa + ARR);
            }
#pragma unroll
            for (int j = 0; j < 8; j++) {
                uint32_t ba = base + 2 * ARR +
                    (uint32_t)(wn + j * 8 + (lane & 7)) * (LDE * 2) +
                    (uint32_t)(k0 + ((lane >> 3) & 1) * 8) * 2;
                unsigned bh[2], bl[2];
                ldsm2(bh, ba);
                ldsm2(bl, ba + ARR);
#pragma unroll
                for (int m = 0; m < 4; m++) {
                    mma16816(acc[m][j], ah[m], bh);
                    mma16816(acc[m][j], ah[m], bl);
                    mma16816(acc[m][j], al[m], bh);
                }
            }
        }
        __syncthreads();
    }

#pragma unroll
    for (int m = 0; m < 4; m++) {
        int r0 = m0 + wm + m * 16 + (lane >> 2);
#pragma unroll
        for (int j = 0; j < 8; j++) {
            int c = n0 + wn + j * 8 + (lane & 3) * 2;
            *(float2*)(C + (size_t)r0 * N + c) = make_float2(acc[m][j][0], acc[m][j][1]);
            *(float2*)(C + (size_t)(r0 + 8) * N + c) = make_float2(acc[m][j][2], acc[m][j][3]);
        }
    }
}

// ---------------- tensorized flash attention (writes bf16 hi/lo) ----------------
#define AQ 128
#define AKV 64
#define LDA 136
#define QARR (128 * LDA * 2)
#define KARR (64 * LDA * 2)
#define KVSTG (4 * KARR)
#define SMEM_ATT (2 * QARR + 2 * KVSTG)   // 208896 B

__global__ __launch_bounds__(256, 1)
void attn_mma(const __nv_bfloat16* __restrict__ Qh, const __nv_bfloat16* __restrict__ Ql,
              const __nv_bfloat16* __restrict__ Kh, const __nv_bfloat16* __restrict__ Kl,
              const __nv_bfloat16* __restrict__ Vh, const __nv_bfloat16* __restrict__ Vl,
              __nv_bfloat16* __restrict__ Oh, __nv_bfloat16* __restrict__ Ol) {
    extern __shared__ char smem[];
    const uint32_t sb = smem_u32(smem);
    const int tid = threadIdx.x;
    const int lane = tid & 31, warp = tid >> 5;
    const int h = blockIdx.y;
    const int qt = (gridDim.x - 1) - blockIdx.x;
    const int q0 = qt * AQ;
    const int kvh = h >> 2;
    const float scale = 0.08838834764831845f;
    const float NEGF = -1e30f;

#pragma unroll
    for (int s = tid; s < 128 * 16; s += 256) {
        int row = s >> 4, c = s & 15;
        uint32_t so = sb + (uint32_t)row * (LDA * 2) + c * 16;
        size_t go = (size_t)(q0 + row) * DIM + h * HD + c * 8;
        cpa16(so, Qh + go);
        cpa16(so + QARR, Ql + go);
    }
    auto load_kv = [&](int buf, int k0) {
        uint32_t b0 = sb + 2 * QARR + buf * KVSTG;
#pragma unroll
        for (int s = tid; s < 1024; s += 256) {
            int row = s >> 4, c = s & 15;
            uint32_t so = b0 + (uint32_t)row * (LDA * 2) + c * 16;
            size_t go = (size_t)(k0 + row) * KVD + kvh * HD + c * 8;
            cpa16(so, Kh + go);
            cpa16(so + KARR, Kl + go);
            cpa16(so + 2 * KARR, Vh + go);
            cpa16(so + 3 * KARR, Vl + go);
        }
        asm volatile("cp.async.commit_group;");
    };
    load_kv(0, 0);

    const int rA = q0 + warp * 16 + (lane >> 2);
    const int qwmax = q0 + warp * 16 + 15;
    float mA = NEGF, mB = NEGF, lA = 0.f, lB = 0.f;
    float o[16][4];
#pragma unroll
    for (int j = 0; j < 16; j++)
#pragma unroll
        for (int v = 0; v < 4; v++) o[j][v] = 0.f;

    const int ntiles = (q0 + AQ) / AKV;
#pragma unroll 1
    for (int t = 0; t < ntiles; t++) {
        const int k0 = t * AKV;
        if (t + 1 < ntiles) {
            load_kv((t + 1) & 1, (t + 1) * AKV);
            asm volatile("cp.async.wait_group 1;");
        } else {
            asm volatile("cp.async.wait_group 0;");
        }
        __syncthreads();

        if (k0 <= qwmax) {
            const uint32_t kb = sb + 2 * QARR + (t & 1) * KVSTG;
            const uint32_t vb = kb + 2 * KARR;

            float s[8][4];
#pragma unroll
            for (int j = 0; j < 8; j++)
#pragma unroll
                for (int v = 0; v < 4; v++) s[j][v] = 0.f;

#pragma unroll
            for (int kc = 0; kc < 8; kc++) {
                uint32_t qa = sb + (uint32_t)(warp * 16 + (lane & 15)) * (LDA * 2) +
                              (uint32_t)(kc * 16 + (lane >> 4) * 8) * 2;
                unsigned aqh[4], aql[4];
                ldsm4(aqh, qa);
                ldsm4(aql, qa + QARR);
#pragma unroll
                for (int j = 0; j < 8; j++) {
                    uint32_t ka = kb + (uint32_t)(j * 8 + (lane & 7)) * (LDA * 2) +
                                  (uint32_t)(kc * 16 + ((lane >> 3) & 1) * 8) * 2;
                    unsigned bkh[2], bkl[2];
                    ldsm2(bkh, ka);
                    ldsm2(bkl, ka + KARR);
                    mma16816(s[j], aqh, bkh);
                    mma16816(s[j], aqh, bkl);
                    mma16816(s[j], aql, bkh);
                }
            }

            const bool need_mask = (k0 + AKV - 1) > (q0 + warp * 16);
#pragma unroll
            for (int j = 0; j < 8; j++) {
#pragma unroll
                for (int v = 0; v < 4; v++) s[j][v] *= scale;
                if (need_mask) {
                    int cg = k0 + j * 8 + (lane & 3) * 2;
                    if (cg > rA) s[j][0] = NEGF;
                    if (cg + 1 > rA) s[j][1] = NEGF;
                    if (cg > rA + 8) s[j][2] = NEGF;
                    if (cg + 1 > rA + 8) s[j][3] = NEGF;
                }
            }

            float mxA = NEGF, mxB = NEGF;
#pragma unroll
            for (int j = 0; j < 8; j++) {
                mxA = fmaxf(mxA, fmaxf(s[j][0], s[j][1]));
                mxB = fmaxf(mxB, fmaxf(s[j][2], s[j][3]));
            }
            mxA = fmaxf(mxA, __shfl_xor_sync(0xffffffffu, mxA, 1));
            mxA = fmaxf(mxA, __shfl_xor_sync(0xffffffffu, mxA, 2));
            mxB = fmaxf(mxB, __shfl_xor_sync(0xffffffffu, mxB, 1));
            mxB = fmaxf(mxB, __shfl_xor_sync(0xffffffffu, mxB, 2));
            float mAn = fmaxf(mA, mxA), mBn = fmaxf(mB, mxB);
            float fA = __expf(mA - mAn), fB = __expf(mB - mBn);
            float sA = 0.f, sB = 0.f;
#pragma unroll
            for (int j = 0; j < 8; j++) {
                s[j][0] = __expf(s[j][0] - mAn);
                s[j][1] = __expf(s[j][1] - mAn);
                s[j][2] = __expf(s[j][2] - mBn);
                s[j][3] = __expf(s[j][3] - mBn);
                sA += s[j][0] + s[j][1];
                sB += s[j][2] + s[j][3];
            }
            sA += __shfl_xor_sync(0xffffffffu, sA, 1);
            sA += __shfl_xor_sync(0xffffffffu, sA, 2);
            sB += __shfl_xor_sync(0xffffffffu, sB, 1);
            sB += __shfl_xor_sync(0xffffffffu, sB, 2);
            lA = lA * fA + sA;
            lB = lB * fB + sB;
            mA = mAn;
            mB = mBn;
#pragma unroll
            for (int j = 0; j < 16; j++) {
                o[j][0] *= fA;
                o[j][1] *= fA;
                o[j][2] *= fB;
                o[j][3] *= fB;
            }

#pragma unroll
            for (int kc = 0; kc < 4; kc++) {
                const int j0 = 2 * kc, j1 = 2 * kc + 1;
                unsigned ph[4], pl[4];
                ph[0] = pack_bf2(s[j0][0], s[j0][1]);
                ph[1] = pack_bf2(s[j0][2], s[j0][3]);
                ph[2] = pack_bf2(s[j1][0], s[j1][1]);
                ph[3] = pack_bf2(s[j1][2], s[j1][3]);
                pl[0] = pack_bf2(s[j0][0] - bf2lo(ph[0]), s[j0][1] - bf2hi(ph[0]));
                pl[1] = pack_bf2(s[j0][2] - bf2lo(ph[1]), s[j0][3] - bf2hi(ph[1]));
                pl[2] = pack_bf2(s[j1][0] - bf2lo(ph[2]), s[j1][1] - bf2hi(ph[2]));
                pl[3] = pack_bf2(s[j1][2] - bf2lo(ph[3]), s[j1][3] - bf2hi(ph[3]));
#pragma unroll
                for (int j = 0; j < 16; j++) {
                    uint32_t va = vb + (uint32_t)(kc * 16 + (lane & 15)) * (LDA * 2) +
                                  (uint32_t)(j * 8) * 2;
                    unsigned bvh[2], bvl[2];
                    ldsm2t(bvh, va);
                    ldsm2t(bvl, va + KARR);
                    mma16816(o[j], ph, bvh);
                    mma16816(o[j], ph, bvl);
                    mma16816(o[j], pl, bvh);
                }
            }
        }
        __syncthreads();
    }

    // epilogue: normalize, split to bf16 hi/lo, write packed pairs
    float rlA = 1.0f / lA, rlB = 1.0f / lB;
#pragma unroll
    for (int j = 0; j < 16; j++) {
        int c = h * HD + j * 8 + (lane & 3) * 2;
        float a0 = o[j][0] * rlA, a1 = o[j][1] * rlA;
        float b0 = o[j][2] * rlB, b1 = o[j][3] * rlB;
        unsigned hA = pack_bf2(a0, a1);
        unsigned lAp = pack_bf2(a0 - bf2lo(hA), a1 - bf2hi(hA));
        unsigned hB = pack_bf2(b0, b1);
        unsigned lBp = pack_bf2(b0 - bf2lo(hB), b1 - bf2hi(hB));
        *(unsigned*)(Oh + (size_t)rA * DIM + c) = hA;
        *(unsigned*)(Ol + (size_t)rA * DIM + c) = lAp;
        *(unsigned*)(Oh + (size_t)(rA + 8) * DIM + c) = hB;
        *(unsigned*)(Ol + (size_t)(rA + 8) * DIM + c) = lBp;
    }
}

// ---------------- launch --------------------------------------------------------
extern "C" void kernel_launch(void* const* d_in, const int* in_sizes, int n_in,
                              void* d_out, int out_size) {
    const float* x  = (const float*)d_in[0];
    const float* wq = (const float*)d_in[1];
    const float* wk = (const float*)d_in[2];
    const float* wv = (const float*)d_in[3];
    const float* wo = (const float*)d_in[4];
    const float* fc = (const float*)d_in[5];
    const float* fs = (const float*)d_in[6];
    float* out = (float*)d_out;

    float* xqkv;
    cudaGetSymbolAddress((void**)&xqkv, g_xqkv);
    __nv_bfloat16 *xh, *xl, *ah, *al, *qh, *ql, *kh, *kl, *vh, *vl, *wh, *wl, *woh, *wol;
    cudaGetSymbolAddress((void**)&xh, g_xh);
    cudaGetSymbolAddress((void**)&xl, g_xl);
    cudaGetSymbolAddress((void**)&ah, g_ah);
    cudaGetSymbolAddress((void**)&al, g_al);
    cudaGetSymbolAddress((void**)&qh, g_qh);
    cudaGetSymbolAddress((void**)&ql, g_ql);
    cudaGetSymbolAddress((void**)&kh, g_kh);
    cudaGetSymbolAddress((void**)&kl, g_kl);
    cudaGetSymbolAddress((void**)&vh, g_vh);
    cudaGetSymbolAddress((void**)&vl, g_vl);
    cudaGetSymbolAddress((void**)&wh, g_wh);
    cudaGetSymbolAddress((void**)&wl, g_wl);
    cudaGetSymbolAddress((void**)&woh, g_woh);
    cudaGetSymbolAddress((void**)&wol, g_wol);

    dim3 tsb(32, 8);
    transpose_split_qkv<<<dim3(NQKV / 32, DIM / 32), tsb>>>(wq, wk, wv, wh, wl);
    transpose_split<<<dim3(DIM / 32, DIM / 32), tsb>>>(wo, woh, wol, DIM, DIM);
    split_kernel<<<(SEQ * DIM + 255) / 256, 256>>>(x, xh, xl, SEQ * DIM);

    cudaFuncSetAttribute(gemm_hmma, cudaFuncAttributeMaxDynamicSharedMemorySize, SMEM_GEMM);
    gemm_hmma<<<dim3(NQKV / BN, SEQ / BM), 128, SMEM_GEMM>>>(xh, xl, wh, wl, xqkv,
                                                             SEQ, NQKV, DIM);

    postproc_kernel<<<(SEQ * 3072 + 255) / 256, 256>>>(xqkv, fc, fs, qh, ql, kh, kl, vh, vl);

    cudaFuncSetAttribute(attn_mma, cudaFuncAttributeMaxDynamicSharedMemorySize, SMEM_ATT);
    attn_mma<<<dim3(SEQ / AQ, NH), 256, SMEM_ATT>>>(qh, ql, kh, kl, vh, vl, ah, al);

    gemm_hmma<<<dim3(DIM / BN, SEQ / BM), 128, SMEM_GEMM>>>(ah, al, woh, wol, out,
                                                            SEQ, DIM, DIM);
}